// round 16
// baseline (speedup 1.0000x reference)
#include <cuda_runtime.h>
#include <math.h>

#define BB 64
#define QQ 4096
#define NN 256
#define NL 21
#define QT  128                  // q rows per block
#define INF_REPLACE 1000000.0f
// Conservative gate on expanded d^2 = |p|^2 - 2 p.t + |t|^2 (fp32 magnitudes
// <= ~1.5e4 -> rounding error << 1/16). Every pair with true d^2 <= 4 passes;
// gated-in pairs are decided by the exact reference computation
// (dist = sqrt(sum((p-t)^2)) <= 2), so boundary decisions match the reference.
#define THR_FAST 4.0625f

// ---- slow path: exact re-decision + cost for one thread's 4 targets --------
// Rare (~0.9% of warp-rows). Overwrites the already-stored INF values.
__device__ __noinline__ void patch_quad(
    const float* __restrict__ logits, const int* __restrict__ labels,
    const float* __restrict__ tboxes, const float* __restrict__ pboxes,
    int b, int q, int n0,
    float pcx, float pcy, float pcz,
    float* __restrict__ orow)            // &out[b][q][n0]
{
    const float* pb = pboxes + ((size_t)b * QQ + q) * 6;
    const float psx = __ldg(pb + 3), psy = __ldg(pb + 4), psz = __ldg(pb + 5);

    #pragma unroll
    for (int j = 0; j < 4; j++) {
        const float* tb = tboxes + ((size_t)b * NN + n0 + j) * 6;
        const float tcx = __ldg(tb + 0), tcy = __ldg(tb + 1), tcz = __ldg(tb + 2);
        // exact reference arithmetic
        const float dx = pcx - tcx, dy = pcy - tcy, dz = pcz - tcz;
        const float d2 = dx*dx + dy*dy + dz*dz;
        const float dist = sqrtf(d2);
        if (dist > 2.0f) continue;

        const float tsx = __ldg(tb + 3), tsy = __ldg(tb + 4), tsz = __ldg(tb + 5);
        float ix = fminf(pcx + 0.5f*psx, tcx + 0.5f*tsx) - fmaxf(pcx - 0.5f*psx, tcx - 0.5f*tsx);
        float iy = fminf(pcy + 0.5f*psy, tcy + 0.5f*tsy) - fmaxf(pcy - 0.5f*psy, tcy - 0.5f*tsy);
        float iz = fminf(pcz + 0.5f*psz, tcz + 0.5f*tsz) - fmaxf(pcz - 0.5f*psz, tcz - 0.5f*tsz);
        ix = fmaxf(ix, 0.0f); iy = fmaxf(iy, 0.0f); iz = fmaxf(iz, 0.0f);

        const float inter = ix * iy * iz;
        const float vol1 = psx * psy * psz;
        const float vol2 = tsx * tsy * tsz;
        const float uni  = vol1 + vol2 - inter;
        const float iou  = (uni > 0.0f) ? (inter / uni) : 0.0f;

        const float* lg = logits + ((size_t)b * QQ + q) * NL;
        const int lbl = __ldg(labels + b * NN + n0 + j);
        float s = 0.0f, el = 0.0f;
        #pragma unroll
        for (int c = 0; c < NL; c++) {
            const float e = expf(__ldg(lg + c));
            s += e;
            if (c == lbl) el = e;
        }
        const float cls = -(el / s);
        orow[j] = cls + 5.0f * dist + 2.0f * (1.0f - iou);   // overwrite INF
    }
}

// ---------------- single fused kernel ---------------------------------------
__global__ __launch_bounds__(256, 5) void matcher_kernel(
    const float* __restrict__ logits,    // [B, Q, 21]
    const float* __restrict__ pboxes,    // [B, Q, 6]
    const int*   __restrict__ labels,    // [B, N]
    const float* __restrict__ tboxes,    // [B, N, 6]
    float*       __restrict__ out)       // [B, Q, N]
{
    const int b  = blockIdx.y;
    const int q0 = blockIdx.x * QT;
    const int t  = threadIdx.x;
    const int g  = t >> 6;               // 0..3 — row offset (warp-uniform)
    const int u  = t & 63;               // owns targets 4u .. 4u+3

    __shared__ float  s_praw[QT * 6];    // staged pred boxes (raw)
    __shared__ float  s_traw[NN * 6];    // staged target boxes (raw)
    __shared__ float4 s_p[QT];           // (px, py, pz, tq = THR - |p|^2)

    // ---- coalesced staging ----
    {
        const float* pb = pboxes + ((size_t)b * QQ + q0) * 6;
        #pragma unroll
        for (int i = t; i < QT * 6; i += 256) s_praw[i] = pb[i];
        const float* tb = tboxes + (size_t)b * NN * 6;
        #pragma unroll
        for (int i = t; i < NN * 6; i += 256) s_traw[i] = tb[i];
    }
    __syncthreads();

    // per-thread gate constants for the four owned targets (registers only)
    float Ax[4], Ay[4], Az[4], K[4];
    #pragma unroll
    for (int j = 0; j < 4; j++) {
        const int n = 4 * u + j;
        const float x = s_traw[n*6+0], y = s_traw[n*6+1], z = s_traw[n*6+2];
        Ax[j] = -2.0f*x; Ay[j] = -2.0f*y; Az[j] = -2.0f*z;
        K[j]  = x*x + y*y + z*z;
    }

    // per-row broadcast constants
    if (t < QT) {
        const float x = s_praw[t*6+0], y = s_praw[t*6+1], z = s_praw[t*6+2];
        s_p[t] = make_float4(x, y, z, THR_FAST - (x*x + y*y + z*z));
    }
    __syncthreads();

    // ---- main loop: unconditional INF store, rare patch-after ----
    float* obase = out + ((size_t)b * QQ + q0) * NN + 4 * u;
    const float4 vinf = make_float4(INF_REPLACE, INF_REPLACE, INF_REPLACE, INF_REPLACE);

    #pragma unroll 4
    for (int k = 0; k < QT / 4; k++) {
        const int r = 4 * k + g;                        // warp-uniform row
        float* orow = obase + (size_t)r * NN;

        // store INF immediately — no dependency on the gate
        *(float4*)orow = vinf;

        const float4 p = s_p[r];                        // broadcast LDS.128
        const float m0 = fmaf(Ax[0], p.x, fmaf(Ay[0], p.y, fmaf(Az[0], p.z, K[0])));
        const float m1 = fmaf(Ax[1], p.x, fmaf(Ay[1], p.y, fmaf(Az[1], p.z, K[1])));
        const float m2 = fmaf(Ax[2], p.x, fmaf(Ay[2], p.y, fmaf(Az[2], p.z, K[2])));
        const float m3 = fmaf(Ax[3], p.x, fmaf(Ay[3], p.y, fmaf(Az[3], p.z, K[3])));
        const bool near = (fminf(fminf(m0, m1), fminf(m2, m3)) <= p.w);

        if (__any_sync(0xFFFFFFFFu, near)) {            // warp-uniform, rare
            if (near)                                    // same-thread overwrite: ordered
                patch_quad(logits, labels, tboxes, pboxes,
                           b, q0 + r, 4 * u, p.x, p.y, p.z, orow);
        }
    }
}

extern "C" void kernel_launch(void* const* d_in, const int* in_sizes, int n_in,
                              void* d_out, int out_size)
{
    const float* logits = (const float*)d_in[0];  // [B,Q,21]
    const float* pboxes = (const float*)d_in[1];  // [B,Q,6]
    const int*   labels = (const int*)  d_in[2];  // [B,N]
    const float* tboxes = (const float*)d_in[3];  // [B,N,6]
    float*       out    = (float*)d_out;          // [B,Q,N]

    dim3 grid(QQ / QT, BB);                       // (32, 64) = 2048 blocks
    matcher_kernel<<<grid, 256>>>(logits, pboxes, labels, tboxes, out);
}

// round 17
// speedup vs baseline: 1.3833x; 1.3833x over previous
#include <cuda_runtime.h>
#include <math.h>

#define BB 64
#define QQ 4096
#define NN 256
#define NL 21
#define QT  128                  // q rows per block
#define INF_REPLACE 1000000.0f
// Conservative gate on expanded d^2 = |p|^2 - 2 p.t + |t|^2 (fp32 magnitudes
// <= ~1.5e4 -> rounding error << 1/16). Every pair with true d^2 <= 4 passes;
// flagged rows are re-decided with the exact reference computation
// (dist = sqrt(sum((p-t)^2)) <= 2), so boundary decisions match the reference.
#define THR_FAST 4.0625f

// ---- slow path: exact decision + cost for one thread's 4 targets -----------
// Rare (~0.3% of thread-rows). Overwrites the already-stored INF values.
// Checks dist<=2 exactly for each target (subsumes the gate).
__device__ __noinline__ void patch_quad(
    const float* __restrict__ logits, const int* __restrict__ labels,
    const float* __restrict__ tboxes, const float* __restrict__ pboxes,
    int b, int q, int n0,
    float pcx, float pcy, float pcz,
    float* __restrict__ orow)            // &out[b][q][n0]
{
    const float* pb = pboxes + ((size_t)b * QQ + q) * 6;
    const float psx = __ldg(pb + 3), psy = __ldg(pb + 4), psz = __ldg(pb + 5);

    #pragma unroll
    for (int j = 0; j < 4; j++) {
        const float* tb = tboxes + ((size_t)b * NN + n0 + j) * 6;
        const float tcx = __ldg(tb + 0), tcy = __ldg(tb + 1), tcz = __ldg(tb + 2);
        // exact reference arithmetic
        const float dx = pcx - tcx, dy = pcy - tcy, dz = pcz - tcz;
        const float d2 = dx*dx + dy*dy + dz*dz;
        const float dist = sqrtf(d2);
        if (dist > 2.0f) continue;

        const float tsx = __ldg(tb + 3), tsy = __ldg(tb + 4), tsz = __ldg(tb + 5);
        float ix = fminf(pcx + 0.5f*psx, tcx + 0.5f*tsx) - fmaxf(pcx - 0.5f*psx, tcx - 0.5f*tsx);
        float iy = fminf(pcy + 0.5f*psy, tcy + 0.5f*tsy) - fmaxf(pcy - 0.5f*psy, tcy - 0.5f*tsy);
        float iz = fminf(pcz + 0.5f*psz, tcz + 0.5f*tsz) - fmaxf(pcz - 0.5f*psz, tcz - 0.5f*tsz);
        ix = fmaxf(ix, 0.0f); iy = fmaxf(iy, 0.0f); iz = fmaxf(iz, 0.0f);

        const float inter = ix * iy * iz;
        const float vol1 = psx * psy * psz;
        const float vol2 = tsx * tsy * tsz;
        const float uni  = vol1 + vol2 - inter;
        const float iou  = (uni > 0.0f) ? (inter / uni) : 0.0f;

        const float* lg = logits + ((size_t)b * QQ + q) * NL;
        const int lbl = __ldg(labels + b * NN + n0 + j);
        float s = 0.0f, el = 0.0f;
        #pragma unroll
        for (int c = 0; c < NL; c++) {
            const float e = expf(__ldg(lg + c));
            s += e;
            if (c == lbl) el = e;
        }
        const float cls = -(el / s);
        orow[j] = cls + 5.0f * dist + 2.0f * (1.0f - iou);   // overwrite INF
    }
}

// ---------------- single fused kernel ---------------------------------------
__global__ __launch_bounds__(256) void matcher_kernel(
    const float* __restrict__ logits,    // [B, Q, 21]
    const float* __restrict__ pboxes,    // [B, Q, 6]
    const int*   __restrict__ labels,    // [B, N]
    const float* __restrict__ tboxes,    // [B, N, 6]
    float*       __restrict__ out)       // [B, Q, N]
{
    const int b  = blockIdx.y;
    const int q0 = blockIdx.x * QT;
    const int t  = threadIdx.x;
    const int g  = t >> 6;               // 0..3 — row offset (warp-uniform)
    const int u  = t & 63;               // owns targets 4u .. 4u+3

    __shared__ float  s_praw[QT * 6];    // staged pred boxes (raw)
    __shared__ float  s_traw[NN * 6];    // staged target boxes (raw)
    __shared__ float4 s_p[QT];           // (px, py, pz, tq = THR - |p|^2)

    // ---- coalesced staging ----
    {
        const float* pb = pboxes + ((size_t)b * QQ + q0) * 6;
        #pragma unroll
        for (int i = t; i < QT * 6; i += 256) s_praw[i] = pb[i];
        const float* tb = tboxes + (size_t)b * NN * 6;
        #pragma unroll
        for (int i = t; i < NN * 6; i += 256) s_traw[i] = tb[i];
    }
    __syncthreads();

    // per-thread gate constants for the four owned targets (registers only)
    float Ax[4], Ay[4], Az[4], K[4];
    #pragma unroll
    for (int j = 0; j < 4; j++) {
        const int n = 4 * u + j;
        const float x = s_traw[n*6+0], y = s_traw[n*6+1], z = s_traw[n*6+2];
        Ax[j] = -2.0f*x; Ay[j] = -2.0f*y; Az[j] = -2.0f*z;
        K[j]  = x*x + y*y + z*z;
    }

    // per-row broadcast constants
    if (t < QT) {
        const float x = s_praw[t*6+0], y = s_praw[t*6+1], z = s_praw[t*6+2];
        s_p[t] = make_float4(x, y, z, THR_FAST - (x*x + y*y + z*z));
    }
    __syncthreads();

    // ---- main loop: branchless, call-free; INF stream + gate bitmask ----
    float* obase = out + ((size_t)b * QQ + q0) * NN + 4 * u;
    const float4 vinf = make_float4(INF_REPLACE, INF_REPLACE, INF_REPLACE, INF_REPLACE);
    unsigned nearmask = 0;

    #pragma unroll 4
    for (int k = 0; k < QT / 4; k++) {
        const int r = 4 * k + g;                        // warp-uniform row
        float4* orow4 = (float4*)(obase + (size_t)r * NN);

        __stcs(orow4, vinf);                            // streaming store, no deps

        const float4 p = s_p[r];                        // broadcast LDS.128
        const float m0 = fmaf(Ax[0], p.x, fmaf(Ay[0], p.y, fmaf(Az[0], p.z, K[0])));
        const float m1 = fmaf(Ax[1], p.x, fmaf(Ay[1], p.y, fmaf(Az[1], p.z, K[1])));
        const float m2 = fmaf(Ax[2], p.x, fmaf(Ay[2], p.y, fmaf(Az[2], p.z, K[2])));
        const float m3 = fmaf(Ax[3], p.x, fmaf(Ay[3], p.y, fmaf(Az[3], p.z, K[3])));
        const bool near = (fminf(fminf(m0, m1), fminf(m2, m3)) <= p.w);
        nearmask |= near ? (1u << k) : 0u;              // no branch, no vote
    }

    // ---- epilogue: one vote; rare exact patching ----
    if (__any_sync(0xFFFFFFFFu, nearmask != 0u)) {
        while (nearmask) {
            const int k = __ffs(nearmask) - 1;
            nearmask &= nearmask - 1;
            const int r = 4 * k + g;
            const float4 p = s_p[r];
            // same-thread overwrite of the earlier INF store: ordered, safe
            patch_quad(logits, labels, tboxes, pboxes,
                       b, q0 + r, 4 * u, p.x, p.y, p.z,
                       obase + (size_t)r * NN);
        }
    }
}

extern "C" void kernel_launch(void* const* d_in, const int* in_sizes, int n_in,
                              void* d_out, int out_size)
{
    const float* logits = (const float*)d_in[0];  // [B,Q,21]
    const float* pboxes = (const float*)d_in[1];  // [B,Q,6]
    const int*   labels = (const int*)  d_in[2];  // [B,N]
    const float* tboxes = (const float*)d_in[3];  // [B,N,6]
    float*       out    = (float*)d_out;          // [B,Q,N]

    dim3 grid(QQ / QT, BB);                       // (32, 64) = 2048 blocks
    matcher_kernel<<<grid, 256>>>(logits, pboxes, labels, tboxes, out);
}